// round 15
// baseline (speedup 1.0000x reference)
#include <cuda_runtime.h>
#include <cuda_fp16.h>
#include <math.h>
#include <stdint.h>

#define S_LEN 1024
#define BATCH 2
#define HIDV  2048
#define NH    16
#define HD    128
#define RR    64
#define KVC   512
#define QCV   1536
#define NTOK  (BATCH*S_LEN)   /* 2048 */

// ---------------- scratch (static device globals; no allocation) ----------------
__device__ __align__(256) __half g_h16 [NTOK*(size_t)HIDV];
__device__ __align__(256) __half g_ckv16[NTOK*(size_t)KVC];
__device__ __align__(256) __half g_cq16 [NTOK*(size_t)QCV];
__device__ __align__(256) __half g_k16 [NTOK*(size_t)HIDV];
__device__ __align__(256) __half g_v16 [NTOK*(size_t)HIDV];
__device__ __align__(256) __half g_q16 [NTOK*(size_t)HIDV];
__device__ __align__(256) __half g_a16 [NTOK*(size_t)HIDV];
__device__ __align__(256) float  g_wkrT[HD*RR];
#define OFF_DKV 0
#define OFF_UK  (OFF_DKV + KVC*HIDV)
#define OFF_UV  (OFF_UK  + HIDV*KVC)
#define OFF_DQ  (OFF_UV  + HIDV*KVC)
#define OFF_UQ  (OFF_DQ  + QCV*HIDV)
#define OFF_O   (OFF_UQ  + HIDV*QCV)
#define W16_TOTAL (OFF_O + HIDV*HIDV)
__device__ __align__(256) __half g_w16[W16_TOTAL];

// ---------------- PTX helpers ----------------
#define MMA_F16(d, a, b) \
    asm volatile("mma.sync.aligned.m16n8k16.row.col.f32.f16.f16.f32 " \
        "{%0,%1,%2,%3}, {%4,%5,%6,%7}, {%8,%9}, {%0,%1,%2,%3};" \
        : "+f"(d[0]), "+f"(d[1]), "+f"(d[2]), "+f"(d[3]) \
        : "r"(a[0]), "r"(a[1]), "r"(a[2]), "r"(a[3]), "r"(b[0]), "r"(b[1]))

#define LDSM_X4(r0,r1,r2,r3,addr) \
    asm volatile("ldmatrix.sync.aligned.m8n8.x4.shared.b16 {%0,%1,%2,%3}, [%4];" \
        : "=r"(r0),"=r"(r1),"=r"(r2),"=r"(r3) : "r"(addr))
#define LDSM_X4_T(r0,r1,r2,r3,addr) \
    asm volatile("ldmatrix.sync.aligned.m8n8.x4.trans.shared.b16 {%0,%1,%2,%3}, [%4];" \
        : "=r"(r0),"=r"(r1),"=r"(r2),"=r"(r3) : "r"(addr))

#define CP_ASYNC16(dst_sm, src) \
    asm volatile("cp.async.cg.shared.global [%0], [%1], 16;" \
        :: "r"(dst_sm), "l"(src))
#define CP_COMMIT() asm volatile("cp.async.commit_group;" ::: "memory")
#define CP_WAIT(n)  asm volatile("cp.async.wait_group %0;" :: "n"(n) : "memory")

__device__ __forceinline__ uint32_t pack_h2(float a, float b) {
    __half2 h = __floats2half2_rn(a, b);
    return *reinterpret_cast<uint32_t*>(&h);
}

// ---------------------------------------------------------------------------
// Merged fp32 -> fp16 conversion over 7 segments
// ---------------------------------------------------------------------------
struct C7 {
    const float4* s[7];
    __half2*      d[7];
    int cum[8];
};

__global__ void __launch_bounds__(256)
cvt_multi(C7 j)
{
    int i = blockIdx.x * 256 + threadIdx.x;
    if (i >= j.cum[7]) return;
    int k = 0;
    #pragma unroll
    for (int q = 1; q < 7; q++) if (i >= j.cum[q]) k = q;
    int loc = i - j.cum[k];
    float4 v = j.s[k][loc];
    j.d[k][2*loc]   = __floats2half2_rn(v.x, v.y);
    j.d[k][2*loc+1] = __floats2half2_rn(v.z, v.w);
}

// ---------------------------------------------------------------------------
__global__ void __launch_bounds__(256)
wkr_t(const float* __restrict__ Wkr, float* __restrict__ WkrT)
{
    int i = blockIdx.x * 256 + threadIdx.x;
    if (i < HD * RR) {
        int c = i >> 6, r = i & 63;
        WkrT[i] = Wkr[r * HD + c];
    }
}

// ---------------------------------------------------------------------------
// Multi-job fp16 GEMM:  C = A @ B^T + bias (fp32 acc)
// CTA tile 256x128x128, 256 threads (8 warps, warp tile 64x64), 2-stage
// cp.async, 1 CTA/SM. Fragments software-pipelined (double-buffered).
// ---------------------------------------------------------------------------
#define BM 256
#define BN 128
#define BK 128
#define ASTR 136
#define A_HALVES (BM*ASTR)
#define B_HALVES (BN*ASTR)
#define STG_HALVES (A_HALVES + B_HALVES)
#define GEMM_SMEM (2*STG_HALVES*2)       /* 208896 B, 1 CTA/SM */

struct Job {
    const __half* A; const __half* B; const float* bias;
    float* C; __half* C16;
    int K, lda, ldb, ldc;
};

__global__ void __launch_bounds__(256, 1)
gemm_h(Job j0, Job j1, Job j2, int b1, int b2)
{
    extern __shared__ __half smh[];

    int bx = blockIdx.x;
    Job jb; int nOff;
    if (bx < b1)      { jb = j0; nOff = 0;  }
    else if (bx < b2) { jb = j1; nOff = b1; }
    else              { jb = j2; nOff = b2; }

    int K = jb.K, lda = jb.lda, ldb = jb.ldb, ldc = jb.ldc;

    int tid  = threadIdx.x;
    int warp = tid >> 5, lane = tid & 31;
    int wm = (warp >> 1) * 64;
    int wn = (warp & 1) * 64;
    int g  = lane >> 2, tg = lane & 3;

    int m0 = blockIdx.y * BM, n0 = (bx - nOff) * BN;

    int arow = tid >> 4;            // 0..15
    int acol = (tid & 15) * 8;
    const __half* Ag = jb.A + (long)(m0 + arow) * lda + acol;
    const __half* Bg = jb.B + (long)(n0 + arow) * ldb + acol;
    unsigned uBase = (unsigned)__cvta_generic_to_shared(smh);
    unsigned dOff  = (arow * ASTR + acol) * 2;

    float acc[4][8][4];
    #pragma unroll
    for (int i = 0; i < 4; i++)
        #pragma unroll
        for (int j = 0; j < 8; j++)
            #pragma unroll
            for (int r = 0; r < 4; r++) acc[i][j][r] = 0.f;

    int nk = K / BK;

    auto issue = [&](int stage, int k0) {
        unsigned dA = uBase + stage * STG_HALVES * 2 + dOff;
        unsigned dB = dA + A_HALVES * 2;
        #pragma unroll
        for (int i = 0; i < 16; i++)
            CP_ASYNC16(dA + i * 16 * ASTR * 2, Ag + k0 + (long)i * 16 * lda);
        #pragma unroll
        for (int i = 0; i < 8; i++)
            CP_ASYNC16(dB + i * 16 * ASTR * 2, Bg + k0 + (long)i * 16 * ldb);
        CP_COMMIT();
    };

    issue(0, 0);
    CP_WAIT(0);
    __syncthreads();

    int aRow = lane & 15;
    int aK   = (lane >> 4) * 8;
    int bRow = (lane & 7) + ((lane >> 4) & 1) * 8;
    int bK   = ((lane >> 3) & 1) * 8;

    // fragment double buffers
    unsigned fA[2][4][4], fB[2][8][2];

    auto load_frags = [&](unsigned uA, unsigned uB, int kb, int buf) {
        #pragma unroll
        for (int i = 0; i < 4; i++) {
            unsigned ad = uA + ((wm + i*16 + aRow) * ASTR + kb + aK) * 2;
            LDSM_X4(fA[buf][i][0], fA[buf][i][1], fA[buf][i][2], fA[buf][i][3], ad);
        }
        #pragma unroll
        for (int jg = 0; jg < 4; jg++) {
            unsigned bd = uB + ((wn + jg*16 + bRow) * ASTR + kb + bK) * 2;
            LDSM_X4(fB[buf][2*jg][0], fB[buf][2*jg][1],
                    fB[buf][2*jg+1][0], fB[buf][2*jg+1][1], bd);
        }
    };

    for (int t = 0; t < nk; t++) {
        bool more = (t + 1 < nk);
        if (more) issue((t + 1) & 1, (t + 1) * BK);

        unsigned uA = uBase + (t & 1) * STG_HALVES * 2;
        unsigned uB = uA + A_HALVES * 2;

        load_frags(uA, uB, 0, 0);          // prime ks=0

        #pragma unroll
        for (int ks = 0; ks < 8; ks++) {
            int cur = ks & 1, nxt = cur ^ 1;
            if (ks < 7) load_frags(uA, uB, (ks + 1) * 16, nxt);  // prefetch ahead
            #pragma unroll
            for (int i = 0; i < 4; i++)
                #pragma unroll
                for (int j = 0; j < 8; j++)
                    MMA_F16(acc[i][j], fA[cur][i], fB[cur][j]);
        }

        if (more) CP_WAIT(0);
        __syncthreads();
    }

    #pragma unroll
    for (int i = 0; i < 4; i++) {
        int row0 = m0 + wm + i * 16 + g;
        #pragma unroll
        for (int j = 0; j < 8; j++) {
            int col = n0 + wn + j * 8 + tg * 2;
            float c0 = jb.bias ? jb.bias[col] : 0.f;
            float c1 = jb.bias ? jb.bias[col + 1] : 0.f;
            float v00 = acc[i][j][0] + c0, v01 = acc[i][j][1] + c1;
            float v10 = acc[i][j][2] + c0, v11 = acc[i][j][3] + c1;
            if (jb.C) {
                *(float2*)&jb.C[(long)row0 * ldc + col]       = make_float2(v00, v01);
                *(float2*)&jb.C[(long)(row0 + 8) * ldc + col] = make_float2(v10, v11);
            }
            if (jb.C16) {
                *(__half2*)&jb.C16[(long)row0 * ldc + col]       = __floats2half2_rn(v00, v01);
                *(__half2*)&jb.C16[(long)(row0 + 8) * ldc + col] = __floats2half2_rn(v10, v11);
            }
        }
    }
}

// ---------------------------------------------------------------------------
// kr_rope v2 (unchanged)
// ---------------------------------------------------------------------------
#define KR_G 32

__global__ void __launch_bounds__(128)
kr_rope2(const __half* __restrict__ k16, const float* __restrict__ WkrT,
         const float* __restrict__ bkr, float* __restrict__ out)
{
    __shared__ float sW[HD * RR];
    __shared__ float sKV[KR_G * HD];

    int tid = threadIdx.x;
    int warp = tid >> 5, lane = tid & 31;

    #pragma unroll
    for (int i = tid; i < HD * RR; i += 128) sW[i] = WkrT[i];

    const __half2* src = (const __half2*)(k16 + (size_t)blockIdx.x * KR_G * HD);
    #pragma unroll
    for (int i = tid; i < KR_G * HD / 2; i += 128) {
        float2 f = __half22float2(src[i]);
        sKV[2*i] = f.x; sKV[2*i + 1] = f.y;
    }
    __syncthreads();

    float b0 = bkr[lane], b1 = bkr[lane + 32];
    float inv_freq = expf(-(float)lane * 0.28782313662425573f);

    for (int p = warp; p < KR_G; p += 4) {
        const float* kv = &sKV[p * HD];
        float a0 = b0, a1 = b1;
        #pragma unroll 8
        for (int c = 0; c < HD; c++) {
            float kvc = kv[c];
            a0 += kvc * sW[c * RR + lane];
            a1 += kvc * sW[c * RR + lane + 32];
        }
        int gidx = blockIdx.x * KR_G + p;
        int t = gidx >> 4, h = gidx & 15;
        int s = t & (S_LEN - 1);
        float sn, cs;
        sincosf((float)s * inv_freq, &sn, &cs);
        long o = (long)t * (NH * RR) + h * RR + lane;
        out[o]      = a0 * cs - a1 * sn;
        out[o + 32] = a1 * cs + a0 * sn;
    }
}

// ---------------------------------------------------------------------------
// Fused fp16 flash attention (unchanged — passing)
// ---------------------------------------------------------------------------
#define QSTR 136
#define FK 64
#define SH_Q 0
#define SH_K (SH_Q + 128*QSTR)
#define SH_V (SH_K + 2*FK*QSTR)
#define FLASH_SMEM ((SH_V + 2*FK*QSTR) * 2)

__global__ void __launch_bounds__(256, 2)
flash_attn(const __half* __restrict__ Qg, const __half* __restrict__ Kg,
           const __half* __restrict__ Vg, __half* __restrict__ Og, float scale)
{
    extern __shared__ __half smh[];
    unsigned uS = (unsigned)__cvta_generic_to_shared(smh);

    int tid = threadIdx.x;
    int warp = tid >> 5, lane = tid & 31;
    int g = lane >> 2, tg = lane & 3;
    int wm = warp * 16;

    int z  = blockIdx.y;
    int bb = z / NH, hh = z % NH;
    long tok0 = (long)bb * S_LEN + blockIdx.x * 128;
    const __half* Qb = Qg + tok0 * HIDV + hh * HD;
    const __half* Kb = Kg + (long)bb * S_LEN * HIDV + hh * HD;
    const __half* Vb = Vg + (long)bb * S_LEN * HIDV + hh * HD;

    #pragma unroll
    for (int i = 0; i < 8; i++) {
        int s = tid + i * 256;
        int row = s >> 4, ch = s & 15;
        CP_ASYNC16(uS + (SH_Q + row * QSTR + ch * 8) * 2,
                   Qb + (long)row * HIDV + ch * 8);
    }
    CP_COMMIT();

    auto issueKV = [&](int st, int kt) {
        #pragma unroll
        for (int i = 0; i < 4; i++) {
            int s = tid + i * 256;
            int row = s >> 4, ch = s & 15;
            long goff = (long)(kt * FK + row) * HIDV + ch * 8;
            CP_ASYNC16(uS + (SH_K + st * FK * QSTR + row * QSTR + ch * 8) * 2, Kb + goff);
            CP_ASYNC16(uS + (SH_V + st * FK * QSTR + row * QSTR + ch * 8) * 2, Vb + goff);
        }
        CP_COMMIT();
    };
    issueKV(0, 0);

    float m0 = -1e30f, m1 = -1e30f, l0 = 0.f, l1 = 0.f;
    float o[16][4];
    #pragma unroll
    for (int j = 0; j < 16; j++)
        #pragma unroll
        for (int r = 0; r < 4; r++) o[j][r] = 0.f;

    int aRow = lane & 15;
    int aK   = (lane >> 4) * 8;
    int bRow = (lane & 7) + ((lane >> 4) & 1) * 8;
    int bK   = ((lane >> 3) & 1) * 8;
    int vK   = (lane & 7) + ((lane >> 3) & 1) * 8;
    int vN   = ((lane >> 4) & 1) * 8;

    for (int kt = 0; kt < S_LEN / FK; kt++) {
        CP_WAIT(0);
        __syncthreads();
        if (kt + 1 < S_LEN / FK) issueKV((kt + 1) & 1, kt + 1);

        int kOff = SH_K + (kt & 1) * FK * QSTR;
        int vOff = SH_V + (kt & 1) * FK * QSTR;

        float s_acc[8][4];
        #pragma unroll
        for (int j = 0; j < 8; j++)
            #pragma unroll
            for (int r = 0; r < 4; r++) s_acc[j][r] = 0.f;

        #pragma unroll
        for (int ks = 0; ks < 8; ks++) {
            int kb = ks * 16;
            unsigned a[4];
            LDSM_X4(a[0], a[1], a[2], a[3],
                uS + (SH_Q + (wm + aRow) * QSTR + kb + aK) * 2);
            #pragma unroll
            for (int jg = 0; jg < 4; jg++) {
                unsigned p0[2], p1[2];
                LDSM_X4(p0[0], p0[1], p1[0], p1[1],
                    uS + (kOff + (jg*16 + bRow) * QSTR + kb + bK) * 2);
                MMA_F16(s_acc[2*jg],   a, p0);
                MMA_F16(s_acc[2*jg+1], a, p1);
            }
        }

        #pragma unroll
        for (int j = 0; j < 8; j++)
            #pragma unroll
            for (int r = 0; r < 4; r++) s_acc[j][r] *= scale;

        float mx0 = -1e30f, mx1 = -1e30f;
        #pragma unroll
        for (int j = 0; j < 8; j++) {
            mx0 = fmaxf(mx0, fmaxf(s_acc[j][0], s_acc[j][1]));
            mx1 = fmaxf(mx1, fmaxf(s_acc[j][2], s_acc[j][3]));
        }
        mx0 = fmaxf(mx0, __shfl_xor_sync(0xffffffffu, mx0, 1));
        mx0 = fmaxf(mx0, __shfl_xor_sync(0xffffffffu, mx0, 2));
        mx1 = fmaxf(mx1, __shfl_xor_sync(0xffffffffu, mx1, 1));
        mx1 = fmaxf(mx1, __shfl_xor_sync(0xffffffffu, mx1, 2));

        float mn0 = fmaxf(m0, mx0), mn1 = fmaxf(m1, mx1);
        float al0 = __expf(m0 - mn0), al1 = __expf(m1 - mn1);
        float sum0 = 0.f, sum1 = 0.f;
        #pragma unroll
        for (int j = 0; j < 8; j++) {
            float p00 = __expf(s_acc[j][0] - mn0);
            float p01 = __expf(s_acc[j][1] - mn0);
            float p10 = __expf(s_acc[j][2] - mn1);
            float p11 = __expf(s_acc[j][3] - mn1);
            sum0 += p00 + p01; sum1 += p10 + p11;
            s_acc[j][0] = __uint_as_float(pack_h2(p00, p01));
            s_acc[j][1] = __uint_as_float(pack_h2(p10, p11));
        }
        sum0 += __shfl_xor_sync(0xffffffffu, sum0, 1);
        sum0 += __shfl_xor_sync(0xffffffffu, sum0, 2);
        sum1 += __shfl_xor_sync(0xffffffffu, sum1, 1);
        sum1 += __shfl_xor_sync(0xffffffffu, sum1, 2);
        l0 = l0 * al0 + sum0;
        l1 = l1 * al1 + sum1;
        m0 = mn0; m1 = mn1;
        #pragma unroll
        for (int j = 0; j < 16; j++) {
            o[j][0] *= al0; o[j][1] *= al0;
            o[j][2] *= al1; o[j][3] *= al1;
        }

        #pragma unroll
        for (int ks = 0; ks < 4; ks++) {
            int kb = ks * 16;
            unsigned a[4];
            a[0] = __float_as_uint(s_acc[2*ks][0]);
            a[1] = __float_as_uint(s_acc[2*ks][1]);
            a[2] = __float_as_uint(s_acc[2*ks+1][0]);
            a[3] = __float_as_uint(s_acc[2*ks+1][1]);
            #pragma unroll
            for (int ng = 0; ng < 8; ng++) {
                unsigned p0[2], p1[2];
                LDSM_X4_T(p0[0], p0[1], p1[0], p1[1],
                    uS + (vOff + (kb + vK) * QSTR + ng*16 + vN) * 2);
                MMA_F16(o[2*ng],   a, p0);
                MMA_F16(o[2*ng+1], a, p1);
            }
        }
    }

    float inv0 = 1.0f / l0, inv1 = 1.0f / l1;
    __half* Ob = Og + tok0 * HIDV + hh * HD;
    #pragma unroll
    for (int j = 0; j < 16; j++) {
        int col = j * 8 + tg * 2;
        *(__half2*)&Ob[(long)(wm + g) * HIDV + col] =
            __floats2half2_rn(o[j][0] * inv0, o[j][1] * inv0);
        *(__half2*)&Ob[(long)(wm + 8 + g) * HIDV + col] =
            __floats2half2_rn(o[j][2] * inv1, o[j][3] * inv1);
    }
}

// ---------------------------------------------------------------------------
extern "C" void kernel_launch(void* const* d_in, const int* in_sizes, int n_in,
                              void* d_out, int out_size)
{
    const float* hid  = (const float*)d_in[0];
    const float* Wdkv = (const float*)d_in[1];
    const float* bdkv = (const float*)d_in[2];
    const float* Wuk  = (const float*)d_in[3];
    const float* buk  = (const float*)d_in[4];
    const float* Wuv  = (const float*)d_in[5];
    const float* buv  = (const float*)d_in[6];
    const float* Wkr  = (const float*)d_in[7];
    const float* bkr  = (const float*)d_in[8];
    const float* Wdq  = (const float*)d_in[9];
    const float* bdq  = (const float*)d_in[10];
    const float* Wuq  = (const float*)d_in[11];
    const float* buq  = (const float*)d_in[12];
    // d_in[13..14] = W_QR — dead (q_r unused in reference)
    const float* Wo   = (const float*)d_in[15];
    const float* bo   = (const float*)d_in[16];

    float* out  = (float*)d_out;
    float* c_kv = out  + (long)NTOK * HIDV;
    float* kr   = c_kv + (long)NTOK * KVC;

    __half *h16, *ckv16, *cq16, *k16, *v16, *q16, *a16, *w16;
    float  *wkrT;
    cudaGetSymbolAddress((void**)&h16,   g_h16);
    cudaGetSymbolAddress((void**)&ckv16, g_ckv16);
    cudaGetSymbolAddress((void**)&cq16,  g_cq16);
    cudaGetSymbolAddress((void**)&k16,   g_k16);
    cudaGetSymbolAddress((void**)&v16,   g_v16);
    cudaGetSymbolAddress((void**)&q16,   g_q16);
    cudaGetSymbolAddress((void**)&a16,   g_a16);
    cudaGetSymbolAddress((void**)&w16,   g_w16);
    cudaGetSymbolAddress((void**)&wkrT,  g_wkrT);

    const float scale = 0.08838834764831845f;
    static int attr_set = 0;
    if (!attr_set) {
        cudaFuncSetAttribute(gemm_h,
            cudaFuncAttributeMaxDynamicSharedMemorySize, GEMM_SMEM);
        cudaFuncSetAttribute(flash_attn,
            cudaFuncAttributeMaxDynamicSharedMemorySize, FLASH_SMEM);
        attr_set = 1;
    }

    // Launch 1: all fp32->fp16 conversions
    {
        C7 j;
        const float* srcs[7] = { hid, Wdkv, Wuk, Wuv, Wdq, Wuq, Wo };
        __half* dsts[7] = { h16, w16 + OFF_DKV, w16 + OFF_UK, w16 + OFF_UV,
                            w16 + OFF_DQ, w16 + OFF_UQ, w16 + OFF_O };
        int sizes[7] = { NTOK*HIDV, KVC*HIDV, HIDV*KVC, HIDV*KVC,
                         QCV*HIDV, HIDV*QCV, HIDV*HIDV };
        int cum = 0;
        for (int k = 0; k < 7; k++) {
            j.s[k] = (const float4*)srcs[k];
            j.d[k] = (__half2*)dsts[k];
            j.cum[k] = cum;
            cum += sizes[k] / 4;
        }
        j.cum[7] = cum;
        cvt_multi<<<(cum + 255) / 256, 256>>>(j);
    }

    // Launch 2: W_KR transpose
    wkr_t<<<(HD*RR + 255) / 256, 256>>>(Wkr, wkrT);

    // Launch 3 (L1): c_kv + c_q, K=2048. grid 16 x 8
    {
        Job ja = { h16, w16 + OFF_DKV, bdkv, c_kv,   ckv16, HIDV, HIDV, HIDV, KVC };
        Job jb = { h16, w16 + OFF_DQ,  bdq,  nullptr, cq16, HIDV, HIDV, HIDV, QCV };
        gemm_h<<<dim3(16, NTOK/BM), 256, GEMM_SMEM>>>(ja, jb, jb, 4, 16);
    }

    // Launch 4 (L2): k + v (K=512) + q (K=1536). grid 48 x 8
    {
        Job ja = { ckv16, w16 + OFF_UK, buk, nullptr, k16, KVC, KVC, KVC, HIDV };
        Job jb = { ckv16, w16 + OFF_UV, buv, nullptr, v16, KVC, KVC, KVC, HIDV };
        Job jc = { cq16,  w16 + OFF_UQ, buq, nullptr, q16, QCV, QCV, QCV, HIDV };
        gemm_h<<<dim3(48, NTOK/BM), 256, GEMM_SMEM>>>(ja, jb, jc, 16, 32);
    }

    // Launch 5: k_r (+RoPE)
    kr_rope2<<<NTOK * NH / KR_G, 128>>>(k16, wkrT, bkr, kr);

    // Launch 6: fused flash attention
    flash_attn<<<dim3(S_LEN/128, BATCH*NH), 256, FLASH_SMEM>>>(
        q16, k16, v16, a16, scale);

    // Launch 7 (L4): output = attn @ W_O^T + b. grid 16 x 8
    {
        Job ja = { a16, w16 + OFF_O, bo, out, nullptr, HIDV, HIDV, HIDV, HIDV };
        gemm_h<<<dim3(16, NTOK/BM), 256, GEMM_SMEM>>>(ja, ja, ja, 16, 16);
    }
}

// round 16
// speedup vs baseline: 1.0070x; 1.0070x over previous
#include <cuda_runtime.h>
#include <cuda_fp16.h>
#include <math.h>
#include <stdint.h>

#define S_LEN 1024
#define BATCH 2
#define HIDV  2048
#define NH    16
#define HD    128
#define RR    64
#define KVC   512
#define QCV   1536
#define NTOK  (BATCH*S_LEN)   /* 2048 */

// ---------------- scratch (static device globals; no allocation) ----------------
__device__ __align__(256) __half g_h16 [NTOK*(size_t)HIDV];
__device__ __align__(256) __half g_ckv16[NTOK*(size_t)KVC];
__device__ __align__(256) __half g_cq16 [NTOK*(size_t)QCV];
__device__ __align__(256) __half g_k16 [NTOK*(size_t)HIDV];
__device__ __align__(256) __half g_v16 [NTOK*(size_t)HIDV];
__device__ __align__(256) __half g_q16 [NTOK*(size_t)HIDV];
__device__ __align__(256) __half g_a16 [NTOK*(size_t)HIDV];
__device__ __align__(256) float  g_wkrT[HD*RR];
#define OFF_DKV 0
#define OFF_UK  (OFF_DKV + KVC*HIDV)
#define OFF_UV  (OFF_UK  + HIDV*KVC)
#define OFF_DQ  (OFF_UV  + HIDV*KVC)
#define OFF_UQ  (OFF_DQ  + QCV*HIDV)
#define OFF_O   (OFF_UQ  + HIDV*QCV)
#define W16_TOTAL (OFF_O + HIDV*HIDV)
__device__ __align__(256) __half g_w16[W16_TOTAL];

// ---------------- PTX helpers ----------------
#define MMA_F16(d, a, b) \
    asm volatile("mma.sync.aligned.m16n8k16.row.col.f32.f16.f16.f32 " \
        "{%0,%1,%2,%3}, {%4,%5,%6,%7}, {%8,%9}, {%0,%1,%2,%3};" \
        : "+f"(d[0]), "+f"(d[1]), "+f"(d[2]), "+f"(d[3]) \
        : "r"(a[0]), "r"(a[1]), "r"(a[2]), "r"(a[3]), "r"(b[0]), "r"(b[1]))

#define LDSM_X4(r0,r1,r2,r3,addr) \
    asm volatile("ldmatrix.sync.aligned.m8n8.x4.shared.b16 {%0,%1,%2,%3}, [%4];" \
        : "=r"(r0),"=r"(r1),"=r"(r2),"=r"(r3) : "r"(addr))
#define LDSM_X4_T(r0,r1,r2,r3,addr) \
    asm volatile("ldmatrix.sync.aligned.m8n8.x4.trans.shared.b16 {%0,%1,%2,%3}, [%4];" \
        : "=r"(r0),"=r"(r1),"=r"(r2),"=r"(r3) : "r"(addr))

#define CP_ASYNC16(dst_sm, src) \
    asm volatile("cp.async.cg.shared.global [%0], [%1], 16;" \
        :: "r"(dst_sm), "l"(src))
#define CP_COMMIT() asm volatile("cp.async.commit_group;" ::: "memory")
#define CP_WAIT(n)  asm volatile("cp.async.wait_group %0;" :: "n"(n) : "memory")

// ---------------------------------------------------------------------------
// Merged fp32 -> fp16 conversion over 7 segments
// ---------------------------------------------------------------------------
struct C7 {
    const float4* s[7];
    __half2*      d[7];
    int cum[8];
};

__global__ void __launch_bounds__(256)
cvt_multi(C7 j)
{
    int i = blockIdx.x * 256 + threadIdx.x;
    if (i >= j.cum[7]) return;
    int k = 0;
    #pragma unroll
    for (int q = 1; q < 7; q++) if (i >= j.cum[q]) k = q;
    int loc = i - j.cum[k];
    float4 v = j.s[k][loc];
    j.d[k][2*loc]   = __floats2half2_rn(v.x, v.y);
    j.d[k][2*loc+1] = __floats2half2_rn(v.z, v.w);
}

// ---------------------------------------------------------------------------
__global__ void __launch_bounds__(256)
wkr_t(const float* __restrict__ Wkr, float* __restrict__ WkrT)
{
    int i = blockIdx.x * 256 + threadIdx.x;
    if (i < HD * RR) {
        int c = i >> 6, r = i & 63;
        WkrT[i] = Wkr[r * HD + c];
    }
}

// ---------------------------------------------------------------------------
// Multi-job fp16 GEMM (exact R12 best-measured config):
// CTA tile 256x128x64, 256 threads (8 warps, warp tile 64x64), 3-stage cp.async.
// ---------------------------------------------------------------------------
#define BM 256
#define BN 128
#define BK 64
#define ASTR 72
#define A_HALVES (BM*ASTR)
#define B_HALVES (BN*ASTR)
#define STG_HALVES (A_HALVES + B_HALVES)
#define GEMM_SMEM (3*STG_HALVES*2)      /* 165888 B, 1 CTA/SM */

struct Job {
    const __half* A; const __half* B; const float* bias;
    float* C; __half* C16;
    int K, lda, ldb, ldc;
};

__global__ void __launch_bounds__(256, 1)
gemm_h(Job j0, Job j1, Job j2, int b1, int b2)
{
    extern __shared__ __half smh[];

    int bx = blockIdx.x;
    Job jb; int nOff;
    if (bx < b1)      { jb = j0; nOff = 0;  }
    else if (bx < b2) { jb = j1; nOff = b1; }
    else              { jb = j2; nOff = b2; }

    int K = jb.K, lda = jb.lda, ldb = jb.ldb, ldc = jb.ldc;

    int tid  = threadIdx.x;
    int warp = tid >> 5, lane = tid & 31;
    int wm = (warp >> 1) * 64;
    int wn = (warp & 1) * 64;
    int g  = lane >> 2, tg = lane & 3;

    int m0 = blockIdx.y * BM, n0 = (bx - nOff) * BN;

    int arow = tid >> 3;            // 0..31
    int acol = (tid & 7) * 8;       // halves
    const __half* Ag = jb.A + (long)(m0 + arow) * lda + acol;
    const __half* Bg = jb.B + (long)(n0 + arow) * ldb + acol;
    unsigned uBase = (unsigned)__cvta_generic_to_shared(smh);
    unsigned dOff  = (arow * ASTR + acol) * 2;

    float acc[4][8][4];
    #pragma unroll
    for (int i = 0; i < 4; i++)
        #pragma unroll
        for (int j = 0; j < 8; j++)
            #pragma unroll
            for (int r = 0; r < 4; r++) acc[i][j][r] = 0.f;

    int nk = K / BK;

    auto issue = [&](int stage, int k0) {
        unsigned dA = uBase + stage * STG_HALVES * 2 + dOff;
        unsigned dB = dA + A_HALVES * 2;
        #pragma unroll
        for (int i = 0; i < 8; i++)
            CP_ASYNC16(dA + i * 32 * ASTR * 2, Ag + k0 + (long)i * 32 * lda);
        #pragma unroll
        for (int i = 0; i < 4; i++)
            CP_ASYNC16(dB + i * 32 * ASTR * 2, Bg + k0 + (long)i * 32 * ldb);
        CP_COMMIT();
    };

    issue(0, 0);
    if (nk > 1) issue(1, BK);
    if (nk > 1) CP_WAIT(1); else CP_WAIT(0);
    __syncthreads();

    int aRow = lane & 15;
    int aK   = (lane >> 4) * 8;
    int bRow = (lane & 7) + ((lane >> 4) & 1) * 8;
    int bK   = ((lane >> 3) & 1) * 8;

    for (int t = 0; t < nk; t++) {
        bool more = (t + 2 < nk);
        if (more) issue((t + 2) % 3, (t + 2) * BK);

        unsigned uA = uBase + (t % 3) * STG_HALVES * 2;
        unsigned uB = uA + A_HALVES * 2;

        #pragma unroll
        for (int ks = 0; ks < 4; ks++) {
            int kb = ks * 16;
            unsigned a[4][4], b[8][2];
            #pragma unroll
            for (int i = 0; i < 4; i++) {
                unsigned ad = uA + ((wm + i*16 + aRow) * ASTR + kb + aK) * 2;
                LDSM_X4(a[i][0], a[i][1], a[i][2], a[i][3], ad);
            }
            #pragma unroll
            for (int jg = 0; jg < 4; jg++) {
                unsigned bd = uB + ((wn + jg*16 + bRow) * ASTR + kb + bK) * 2;
                LDSM_X4(b[2*jg][0], b[2*jg][1], b[2*jg+1][0], b[2*jg+1][1], bd);
            }
            #pragma unroll
            for (int i = 0; i < 4; i++)
                #pragma unroll
                for (int j = 0; j < 8; j++)
                    MMA_F16(acc[i][j], a[i], b[j]);
        }

        if (more) CP_WAIT(1); else CP_WAIT(0);
        __syncthreads();
    }

    #pragma unroll
    for (int i = 0; i < 4; i++) {
        int row0 = m0 + wm + i * 16 + g;
        #pragma unroll
        for (int j = 0; j < 8; j++) {
            int col = n0 + wn + j * 8 + tg * 2;
            float c0 = jb.bias ? jb.bias[col] : 0.f;
            float c1 = jb.bias ? jb.bias[col + 1] : 0.f;
            float v00 = acc[i][j][0] + c0, v01 = acc[i][j][1] + c1;
            float v10 = acc[i][j][2] + c0, v11 = acc[i][j][3] + c1;
            if (jb.C) {
                *(float2*)&jb.C[(long)row0 * ldc + col]       = make_float2(v00, v01);
                *(float2*)&jb.C[(long)(row0 + 8) * ldc + col] = make_float2(v10, v11);
            }
            if (jb.C16) {
                *(__half2*)&jb.C16[(long)row0 * ldc + col]       = __floats2half2_rn(v00, v01);
                *(__half2*)&jb.C16[(long)(row0 + 8) * ldc + col] = __floats2half2_rn(v10, v11);
            }
        }
    }
}

// ---------------------------------------------------------------------------
// kr_rope v2 (unchanged)
// ---------------------------------------------------------------------------
#define KR_G 32

__global__ void __launch_bounds__(128)
kr_rope2(const __half* __restrict__ k16, const float* __restrict__ WkrT,
         const float* __restrict__ bkr, float* __restrict__ out)
{
    __shared__ float sW[HD * RR];
    __shared__ float sKV[KR_G * HD];

    int tid = threadIdx.x;
    int warp = tid >> 5, lane = tid & 31;

    #pragma unroll
    for (int i = tid; i < HD * RR; i += 128) sW[i] = WkrT[i];

    const __half2* src = (const __half2*)(k16 + (size_t)blockIdx.x * KR_G * HD);
    #pragma unroll
    for (int i = tid; i < KR_G * HD / 2; i += 128) {
        float2 f = __half22float2(src[i]);
        sKV[2*i] = f.x; sKV[2*i + 1] = f.y;
    }
    __syncthreads();

    float b0 = bkr[lane], b1 = bkr[lane + 32];
    float inv_freq = expf(-(float)lane * 0.28782313662425573f);

    for (int p = warp; p < KR_G; p += 4) {
        const float* kv = &sKV[p * HD];
        float a0 = b0, a1 = b1;
        #pragma unroll 8
        for (int c = 0; c < HD; c++) {
            float kvc = kv[c];
            a0 += kvc * sW[c * RR + lane];
            a1 += kvc * sW[c * RR + lane + 32];
        }
        int gidx = blockIdx.x * KR_G + p;
        int t = gidx >> 4, h = gidx & 15;
        int s = t & (S_LEN - 1);
        float sn, cs;
        sincosf((float)s * inv_freq, &sn, &cs);
        long o = (long)t * (NH * RR) + h * RR + lane;
        out[o]      = a0 * cs - a1 * sn;
        out[o + 32] = a1 * cs + a0 * sn;
    }
}

// ---------------------------------------------------------------------------
// Fused fp16 flash attention — softmax in log2 domain with h2exp2 (MUFU halved).
// ---------------------------------------------------------------------------
#define QSTR 136
#define FK 64
#define SH_Q 0
#define SH_K (SH_Q + 128*QSTR)
#define SH_V (SH_K + 2*FK*QSTR)
#define FLASH_SMEM ((SH_V + 2*FK*QSTR) * 2)

__global__ void __launch_bounds__(256, 2)
flash_attn(const __half* __restrict__ Qg, const __half* __restrict__ Kg,
           const __half* __restrict__ Vg, __half* __restrict__ Og, float scale2)
{
    extern __shared__ __half smh[];
    unsigned uS = (unsigned)__cvta_generic_to_shared(smh);

    int tid = threadIdx.x;
    int warp = tid >> 5, lane = tid & 31;
    int g = lane >> 2, tg = lane & 3;
    int wm = warp * 16;

    int z  = blockIdx.y;
    int bb = z / NH, hh = z % NH;
    long tok0 = (long)bb * S_LEN + blockIdx.x * 128;
    const __half* Qb = Qg + tok0 * HIDV + hh * HD;
    const __half* Kb = Kg + (long)bb * S_LEN * HIDV + hh * HD;
    const __half* Vb = Vg + (long)bb * S_LEN * HIDV + hh * HD;

    #pragma unroll
    for (int i = 0; i < 8; i++) {
        int s = tid + i * 256;
        int row = s >> 4, ch = s & 15;
        CP_ASYNC16(uS + (SH_Q + row * QSTR + ch * 8) * 2,
                   Qb + (long)row * HIDV + ch * 8);
    }
    CP_COMMIT();

    auto issueKV = [&](int st, int kt) {
        #pragma unroll
        for (int i = 0; i < 4; i++) {
            int s = tid + i * 256;
            int row = s >> 4, ch = s & 15;
            long goff = (long)(kt * FK + row) * HIDV + ch * 8;
            CP_ASYNC16(uS + (SH_K + st * FK * QSTR + row * QSTR + ch * 8) * 2, Kb + goff);
            CP_ASYNC16(uS + (SH_V + st * FK * QSTR + row * QSTR + ch * 8) * 2, Vb + goff);
        }
        CP_COMMIT();
    };
    issueKV(0, 0);

    float m0 = -1e30f, m1 = -1e30f, l0 = 0.f, l1 = 0.f;   // log2-domain maxima
    float o[16][4];
    #pragma unroll
    for (int j = 0; j < 16; j++)
        #pragma unroll
        for (int r = 0; r < 4; r++) o[j][r] = 0.f;

    int aRow = lane & 15;
    int aK   = (lane >> 4) * 8;
    int bRow = (lane & 7) + ((lane >> 4) & 1) * 8;
    int bK   = ((lane >> 3) & 1) * 8;
    int vK   = (lane & 7) + ((lane >> 3) & 1) * 8;
    int vN   = ((lane >> 4) & 1) * 8;

    for (int kt = 0; kt < S_LEN / FK; kt++) {
        CP_WAIT(0);
        __syncthreads();
        if (kt + 1 < S_LEN / FK) issueKV((kt + 1) & 1, kt + 1);

        int kOff = SH_K + (kt & 1) * FK * QSTR;
        int vOff = SH_V + (kt & 1) * FK * QSTR;

        float s_acc[8][4];
        #pragma unroll
        for (int j = 0; j < 8; j++)
            #pragma unroll
            for (int r = 0; r < 4; r++) s_acc[j][r] = 0.f;

        #pragma unroll
        for (int ks = 0; ks < 8; ks++) {
            int kb = ks * 16;
            unsigned a[4];
            LDSM_X4(a[0], a[1], a[2], a[3],
                uS + (SH_Q + (wm + aRow) * QSTR + kb + aK) * 2);
            #pragma unroll
            for (int jg = 0; jg < 4; jg++) {
                unsigned p0[2], p1[2];
                LDSM_X4(p0[0], p0[1], p1[0], p1[1],
                    uS + (kOff + (jg*16 + bRow) * QSTR + kb + bK) * 2);
                MMA_F16(s_acc[2*jg],   a, p0);
                MMA_F16(s_acc[2*jg+1], a, p1);
            }
        }

        // scale2 = (1/sqrt(D)) * log2(e): work in log2 domain
        #pragma unroll
        for (int j = 0; j < 8; j++)
            #pragma unroll
            for (int r = 0; r < 4; r++) s_acc[j][r] *= scale2;

        float mx0 = -1e30f, mx1 = -1e30f;
        #pragma unroll
        for (int j = 0; j < 8; j++) {
            mx0 = fmaxf(mx0, fmaxf(s_acc[j][0], s_acc[j][1]));
            mx1 = fmaxf(mx1, fmaxf(s_acc[j][2], s_acc[j][3]));
        }
        mx0 = fmaxf(mx0, __shfl_xor_sync(0xffffffffu, mx0, 1));
        mx0 = fmaxf(mx0, __shfl_xor_sync(0xffffffffu, mx0, 2));
        mx1 = fmaxf(mx1, __shfl_xor_sync(0xffffffffu, mx1, 1));
        mx1 = fmaxf(mx1, __shfl_xor_sync(0xffffffffu, mx1, 2));

        float mn0 = fmaxf(m0, mx0), mn1 = fmaxf(m1, mx1);
        float al0 = exp2f(m0 - mn0), al1 = exp2f(m1 - mn1);
        float sum0 = 0.f, sum1 = 0.f;
        #pragma unroll
        for (int j = 0; j < 8; j++) {
            // p-pair = exp2 of (s - mn), computed packed in fp16 (single MUFU op per pair)
            __half2 e0 = h2exp2(__floats2half2_rn(s_acc[j][0] - mn0, s_acc[j][1] - mn0));
            __half2 e1 = h2exp2(__floats2half2_rn(s_acc[j][2] - mn1, s_acc[j][3] - mn1));
            float2 f0 = __half22float2(e0);
            float2 f1 = __half22float2(e1);
            sum0 += f0.x + f0.y;
            sum1 += f1.x + f1.y;
            s_acc[j][0] = __uint_as_float(*(uint32_t*)&e0);   // P A-frag (rows g, g+8)
            s_acc[j][1] = __uint_as_float(*(uint32_t*)&e1);
        }
        sum0 += __shfl_xor_sync(0xffffffffu, sum0, 1);
        sum0 += __shfl_xor_sync(0xffffffffu, sum0, 2);
        sum1 += __shfl_xor_sync(0xffffffffu, sum1, 1);
        sum1 += __shfl_xor_sync(0xffffffffu, sum1, 2);
        l0 = l0 * al0 + sum0;
        l1 = l1 * al1 + sum1;
        m0 = mn0; m1 = mn1;
        #pragma unroll
        for (int j = 0; j < 16; j++) {
            o[j][0] *= al0; o[j][1] *= al0;
            o[j][2] *= al1; o[j][3] *= al1;
        }

        #pragma unroll
        for (int ks = 0; ks < 4; ks++) {
            unsigned a[4];
            a[0] = __float_as_uint(s_acc[2*ks][0]);
            a[1] = __float_as_uint(s_acc[2*ks][1]);
            a[2] = __float_as_uint(s_acc[2*ks+1][0]);
            a[3] = __float_as_uint(s_acc[2*ks+1][1]);
            int kb = ks * 16;
            #pragma unroll
            for (int ng = 0; ng < 8; ng++) {
                unsigned p0[2], p1[2];
                LDSM_X4_T(p0[0], p0[1], p1[0], p1[1],
                    uS + (vOff + (kb + vK) * QSTR + ng*16 + vN) * 2);
                MMA_F16(o[2*ng],   a, p0);
                MMA_F16(o[2*ng+1], a, p1);
            }
        }
    }

    float inv0 = 1.0f / l0, inv1 = 1.0f / l1;
    __half* Ob = Og + tok0 * HIDV + hh * HD;
    #pragma unroll
    for (int j = 0; j < 16; j++) {
        int col = j * 8 + tg * 2;
        *(__half2*)&Ob[(long)(wm + g) * HIDV + col] =
            __floats2half2_rn(o[j][0] * inv0, o[j][1] * inv0);
        *(__half2*)&Ob[(long)(wm + 8 + g) * HIDV + col] =
            __floats2half2_rn(o[j][2] * inv1, o[j][3] * inv1);
    }
}

// ---------------------------------------------------------------------------
extern "C" void kernel_launch(void* const* d_in, const int* in_sizes, int n_in,
                              void* d_out, int out_size)
{
    const float* hid  = (const float*)d_in[0];
    const float* Wdkv = (const float*)d_in[1];
    const float* bdkv = (const float*)d_in[2];
    const float* Wuk  = (const float*)d_in[3];
    const float* buk  = (const float*)d_in[4];
    const float* Wuv  = (const float*)d_in[5];
    const float* buv  = (const float*)d_in[6];
    const float* Wkr  = (const float*)d_in[7];
    const float* bkr  = (const float*)d_in[8];
    const float* Wdq  = (const float*)d_in[9];
    const float* bdq  = (const float*)d_in[10];
    const float* Wuq  = (const float*)d_in[11];
    const float* buq  = (const float*)d_in[12];
    // d_in[13..14] = W_QR — dead (q_r unused in reference)
    const float* Wo   = (const float*)d_in[15];
    const float* bo   = (const float*)d_in[16];

    float* out  = (float*)d_out;
    float* c_kv = out  + (long)NTOK * HIDV;
    float* kr   = c_kv + (long)NTOK * KVC;

    __half *h16, *ckv16, *cq16, *k16, *v16, *q16, *a16, *w16;
    float  *wkrT;
    cudaGetSymbolAddress((void**)&h16,   g_h16);
    cudaGetSymbolAddress((void**)&ckv16, g_ckv16);
    cudaGetSymbolAddress((void**)&cq16,  g_cq16);
    cudaGetSymbolAddress((void**)&k16,   g_k16);
    cudaGetSymbolAddress((void**)&v16,   g_v16);
    cudaGetSymbolAddress((void**)&q16,   g_q16);
    cudaGetSymbolAddress((void**)&a16,   g_a16);
    cudaGetSymbolAddress((void**)&w16,   g_w16);
    cudaGetSymbolAddress((void**)&wkrT,  g_wkrT);

    // 1/sqrt(128) * log2(e)
    const float scale2 = 0.08838834764831845f * 1.4426950408889634f;
    static int attr_set = 0;
    if (!attr_set) {
        cudaFuncSetAttribute(gemm_h,
            cudaFuncAttributeMaxDynamicSharedMemorySize, GEMM_SMEM);
        cudaFuncSetAttribute(flash_attn,
            cudaFuncAttributeMaxDynamicSharedMemorySize, FLASH_SMEM);
        attr_set = 1;
    }

    // Launch 1: all fp32->fp16 conversions
    {
        C7 j;
        const float* srcs[7] = { hid, Wdkv, Wuk, Wuv, Wdq, Wuq, Wo };
        __half* dsts[7] = { h16, w16 + OFF_DKV, w16 + OFF_UK, w16 + OFF_UV,
                            w16 + OFF_DQ, w16 + OFF_UQ, w16 + OFF_O };
        int sizes[7] = { NTOK*HIDV, KVC*HIDV, HIDV*KVC, HIDV*KVC,
                         QCV*HIDV, HIDV*QCV, HIDV*HIDV };
        int cum = 0;
        for (int k = 0; k < 7; k++) {
            j.s[k] = (const float4*)srcs[k];
            j.d[k] = (__half2*)dsts[k];
            j.cum[k] = cum;
            cum += sizes[k] / 4;
        }
        j.cum[7] = cum;
        cvt_multi<<<(cum + 255) / 256, 256>>>(j);
    }

    // Launch 2: W_KR transpose
    wkr_t<<<(HD*RR + 255) / 256, 256>>>(Wkr, wkrT);

    // Launch 3 (L1): c_kv + c_q, K=2048. grid 16 x 8
    {
        Job ja = { h16, w16 + OFF_DKV, bdkv, c_kv,   ckv16, HIDV, HIDV, HIDV, KVC };
        Job jb = { h16, w16 + OFF_DQ,  bdq,  nullptr, cq16, HIDV, HIDV, HIDV, QCV };
        gemm_h<<<dim3(16, NTOK/BM), 256, GEMM_SMEM>>>(ja, jb, jb, 4, 16);
    }

    // Launch 4 (L2): k + v (K=512) + q (K=1536). grid 48 x 8
    {
        Job ja = { ckv16, w16 + OFF_UK, buk, nullptr, k16, KVC, KVC, KVC, HIDV };
        Job jb = { ckv16, w16 + OFF_UV, buv, nullptr, v16, KVC, KVC, KVC, HIDV };
        Job jc = { cq16,  w16 + OFF_UQ, buq, nullptr, q16, QCV, QCV, QCV, HIDV };
        gemm_h<<<dim3(48, NTOK/BM), 256, GEMM_SMEM>>>(ja, jb, jc, 16, 32);
    }

    // Launch 5: k_r (+RoPE)
    kr_rope2<<<NTOK * NH / KR_G, 128>>>(k16, wkrT, bkr, kr);

    // Launch 6: fused flash attention (log2-domain softmax)
    flash_attn<<<dim3(S_LEN/128, BATCH*NH), 256, FLASH_SMEM>>>(
        q16, k16, v16, a16, scale2);

    // Launch 7 (L4): output = attn @ W_O^T + b. grid 16 x 8
    {
        Job ja = { a16, w16 + OFF_O, bo, out, nullptr, HIDV, HIDV, HIDV, HIDV };
        gemm_h<<<dim3(16, NTOK/BM), 256, GEMM_SMEM>>>(ja, ja, ja, 16, 16);
    }
}

// round 17
// speedup vs baseline: 1.0366x; 1.0294x over previous
#include <cuda_runtime.h>
#include <cuda_fp16.h>
#include <math.h>
#include <stdint.h>

#define S_LEN 1024
#define BATCH 2
#define HIDV  2048
#define NH    16
#define HD    128
#define RR    64
#define KVC   512
#define QCV   1536
#define NTOK  (BATCH*S_LEN)   /* 2048 */

// ---------------- scratch (static device globals; no allocation) ----------------
__device__ __align__(256) __half g_h16 [NTOK*(size_t)HIDV];
__device__ __align__(256) __half g_ckv16[NTOK*(size_t)KVC];
__device__ __align__(256) __half g_cq16 [NTOK*(size_t)QCV];
__device__ __align__(256) __half g_k16 [NTOK*(size_t)HIDV];
__device__ __align__(256) __half g_v16 [NTOK*(size_t)HIDV];
__device__ __align__(256) __half g_q16 [NTOK*(size_t)HIDV];
__device__ __align__(256) __half g_a16 [NTOK*(size_t)HIDV];
__device__ __align__(256) float  g_wkrT[HD*RR];
#define OFF_DKV 0
#define OFF_UK  (OFF_DKV + KVC*HIDV)
#define OFF_UV  (OFF_UK  + HIDV*KVC)
#define OFF_DQ  (OFF_UV  + HIDV*KVC)
#define OFF_UQ  (OFF_DQ  + QCV*HIDV)
#define OFF_O   (OFF_UQ  + HIDV*QCV)
#define W16_TOTAL (OFF_O + HIDV*HIDV)
__device__ __align__(256) __half g_w16[W16_TOTAL];

// ---------------- PTX helpers ----------------
#define MMA_F16(d, a, b) \
    asm volatile("mma.sync.aligned.m16n8k16.row.col.f32.f16.f16.f32 " \
        "{%0,%1,%2,%3}, {%4,%5,%6,%7}, {%8,%9}, {%0,%1,%2,%3};" \
        : "+f"(d[0]), "+f"(d[1]), "+f"(d[2]), "+f"(d[3]) \
        : "r"(a[0]), "r"(a[1]), "r"(a[2]), "r"(a[3]), "r"(b[0]), "r"(b[1]))

#define LDSM_X4(r0,r1,r2,r3,addr) \
    asm volatile("ldmatrix.sync.aligned.m8n8.x4.shared.b16 {%0,%1,%2,%3}, [%4];" \
        : "=r"(r0),"=r"(r1),"=r"(r2),"=r"(r3) : "r"(addr))
#define LDSM_X4_T(r0,r1,r2,r3,addr) \
    asm volatile("ldmatrix.sync.aligned.m8n8.x4.trans.shared.b16 {%0,%1,%2,%3}, [%4];" \
        : "=r"(r0),"=r"(r1),"=r"(r2),"=r"(r3) : "r"(addr))

#define CP_ASYNC16(dst_sm, src) \
    asm volatile("cp.async.cg.shared.global [%0], [%1], 16;" \
        :: "r"(dst_sm), "l"(src))
#define CP_COMMIT() asm volatile("cp.async.commit_group;" ::: "memory")
#define CP_WAIT(n)  asm volatile("cp.async.wait_group %0;" :: "n"(n) : "memory")

// ---------------------------------------------------------------------------
// Merged fp32 -> fp16 conversion over 7 segments
// ---------------------------------------------------------------------------
struct C7 {
    const float4* s[7];
    __half2*      d[7];
    int cum[8];
};

__global__ void __launch_bounds__(256)
cvt_multi(C7 j)
{
    int i = blockIdx.x * 256 + threadIdx.x;
    if (i >= j.cum[7]) return;
    int k = 0;
    #pragma unroll
    for (int q = 1; q < 7; q++) if (i >= j.cum[q]) k = q;
    int loc = i - j.cum[k];
    float4 v = j.s[k][loc];
    j.d[k][2*loc]   = __floats2half2_rn(v.x, v.y);
    j.d[k][2*loc+1] = __floats2half2_rn(v.z, v.w);
}

// ---------------------------------------------------------------------------
__global__ void __launch_bounds__(256)
wkr_t(const float* __restrict__ Wkr, float* __restrict__ WkrT)
{
    int i = blockIdx.x * 256 + threadIdx.x;
    if (i < HD * RR) {
        int c = i >> 6, r = i & 63;
        WkrT[i] = Wkr[r * HD + c];
    }
}

// ---------------------------------------------------------------------------
// Multi-job fp16 GEMM (R12/R16 best-measured config):
// CTA tile 256x128x64, 256 threads (8 warps, warp tile 64x64), 3-stage cp.async.
// ---------------------------------------------------------------------------
#define BM 256
#define BN 128
#define BK 64
#define ASTR 72
#define A_HALVES (BM*ASTR)
#define B_HALVES (BN*ASTR)
#define STG_HALVES (A_HALVES + B_HALVES)
#define GEMM_SMEM (3*STG_HALVES*2)      /* 165888 B, 1 CTA/SM */

struct Job {
    const __half* A; const __half* B; const float* bias;
    float* C; __half* C16;
    int K, lda, ldb, ldc;
};

__global__ void __launch_bounds__(256, 1)
gemm_h(Job j0, Job j1, Job j2, int b1, int b2)
{
    extern __shared__ __half smh[];

    int bx = blockIdx.x;
    Job jb; int nOff;
    if (bx < b1)      { jb = j0; nOff = 0;  }
    else if (bx < b2) { jb = j1; nOff = b1; }
    else              { jb = j2; nOff = b2; }

    int K = jb.K, lda = jb.lda, ldb = jb.ldb, ldc = jb.ldc;

    int tid  = threadIdx.x;
    int warp = tid >> 5, lane = tid & 31;
    int wm = (warp >> 1) * 64;
    int wn = (warp & 1) * 64;
    int g  = lane >> 2, tg = lane & 3;

    int m0 = blockIdx.y * BM, n0 = (bx - nOff) * BN;

    int arow = tid >> 3;
    int acol = (tid & 7) * 8;
    const __half* Ag = jb.A + (long)(m0 + arow) * lda + acol;
    const __half* Bg = jb.B + (long)(n0 + arow) * ldb + acol;
    unsigned uBase = (unsigned)__cvta_generic_to_shared(smh);
    unsigned dOff  = (arow * ASTR + acol) * 2;

    float acc[4][8][4];
    #pragma unroll
    for (int i = 0; i < 4; i++)
        #pragma unroll
        for (int j = 0; j < 8; j++)
            #pragma unroll
            for (int r = 0; r < 4; r++) acc[i][j][r] = 0.f;

    int nk = K / BK;

    auto issue = [&](int stage, int k0) {
        unsigned dA = uBase + stage * STG_HALVES * 2 + dOff;
        unsigned dB = dA + A_HALVES * 2;
        #pragma unroll
        for (int i = 0; i < 8; i++)
            CP_ASYNC16(dA + i * 32 * ASTR * 2, Ag + k0 + (long)i * 32 * lda);
        #pragma unroll
        for (int i = 0; i < 4; i++)
            CP_ASYNC16(dB + i * 32 * ASTR * 2, Bg + k0 + (long)i * 32 * ldb);
        CP_COMMIT();
    };

    issue(0, 0);
    if (nk > 1) issue(1, BK);
    if (nk > 1) CP_WAIT(1); else CP_WAIT(0);
    __syncthreads();

    int aRow = lane & 15;
    int aK   = (lane >> 4) * 8;
    int bRow = (lane & 7) + ((lane >> 4) & 1) * 8;
    int bK   = ((lane >> 3) & 1) * 8;

    for (int t = 0; t < nk; t++) {
        bool more = (t + 2 < nk);
        if (more) issue((t + 2) % 3, (t + 2) * BK);

        unsigned uA = uBase + (t % 3) * STG_HALVES * 2;
        unsigned uB = uA + A_HALVES * 2;

        #pragma unroll
        for (int ks = 0; ks < 4; ks++) {
            int kb = ks * 16;
            unsigned a[4][4], b[8][2];
            #pragma unroll
            for (int i = 0; i < 4; i++) {
                unsigned ad = uA + ((wm + i*16 + aRow) * ASTR + kb + aK) * 2;
                LDSM_X4(a[i][0], a[i][1], a[i][2], a[i][3], ad);
            }
            #pragma unroll
            for (int jg = 0; jg < 4; jg++) {
                unsigned bd = uB + ((wn + jg*16 + bRow) * ASTR + kb + bK) * 2;
                LDSM_X4(b[2*jg][0], b[2*jg][1], b[2*jg+1][0], b[2*jg+1][1], bd);
            }
            #pragma unroll
            for (int i = 0; i < 4; i++)
                #pragma unroll
                for (int j = 0; j < 8; j++)
                    MMA_F16(acc[i][j], a[i], b[j]);
        }

        if (more) CP_WAIT(1); else CP_WAIT(0);
        __syncthreads();
    }

    #pragma unroll
    for (int i = 0; i < 4; i++) {
        int row0 = m0 + wm + i * 16 + g;
        #pragma unroll
        for (int j = 0; j < 8; j++) {
            int col = n0 + wn + j * 8 + tg * 2;
            float c0 = jb.bias ? jb.bias[col] : 0.f;
            float c1 = jb.bias ? jb.bias[col + 1] : 0.f;
            float v00 = acc[i][j][0] + c0, v01 = acc[i][j][1] + c1;
            float v10 = acc[i][j][2] + c0, v11 = acc[i][j][3] + c1;
            if (jb.C) {
                *(float2*)&jb.C[(long)row0 * ldc + col]       = make_float2(v00, v01);
                *(float2*)&jb.C[(long)(row0 + 8) * ldc + col] = make_float2(v10, v11);
            }
            if (jb.C16) {
                *(__half2*)&jb.C16[(long)row0 * ldc + col]       = __floats2half2_rn(v00, v01);
                *(__half2*)&jb.C16[(long)(row0 + 8) * ldc + col] = __floats2half2_rn(v10, v11);
            }
        }
    }
}

// ---------------------------------------------------------------------------
// kr_rope v2 (unchanged)
// ---------------------------------------------------------------------------
#define KR_G 32

__global__ void __launch_bounds__(128)
kr_rope2(const __half* __restrict__ k16, const float* __restrict__ WkrT,
         const float* __restrict__ bkr, float* __restrict__ out)
{
    __shared__ float sW[HD * RR];
    __shared__ float sKV[KR_G * HD];

    int tid = threadIdx.x;
    int warp = tid >> 5, lane = tid & 31;

    #pragma unroll
    for (int i = tid; i < HD * RR; i += 128) sW[i] = WkrT[i];

    const __half2* src = (const __half2*)(k16 + (size_t)blockIdx.x * KR_G * HD);
    #pragma unroll
    for (int i = tid; i < KR_G * HD / 2; i += 128) {
        float2 f = __half22float2(src[i]);
        sKV[2*i] = f.x; sKV[2*i + 1] = f.y;
    }
    __syncthreads();

    float b0 = bkr[lane], b1 = bkr[lane + 32];
    float inv_freq = expf(-(float)lane * 0.28782313662425573f);

    for (int p = warp; p < KR_G; p += 4) {
        const float* kv = &sKV[p * HD];
        float a0 = b0, a1 = b1;
        #pragma unroll 8
        for (int c = 0; c < HD; c++) {
            float kvc = kv[c];
            a0 += kvc * sW[c * RR + lane];
            a1 += kvc * sW[c * RR + lane + 32];
        }
        int gidx = blockIdx.x * KR_G + p;
        int t = gidx >> 4, h = gidx & 15;
        int s = t & (S_LEN - 1);
        float sn, cs;
        sincosf((float)s * inv_freq, &sn, &cs);
        long o = (long)t * (NH * RR) + h * RR + lane;
        out[o]      = a0 * cs - a1 * sn;
        out[o + 32] = a1 * cs + a0 * sn;
    }
}

// ---------------------------------------------------------------------------
// Fused fp16 flash attention (log2-domain softmax, unchanged from R16)
// ---------------------------------------------------------------------------
#define QSTR 136
#define FK 64
#define SH_Q 0
#define SH_K (SH_Q + 128*QSTR)
#define SH_V (SH_K + 2*FK*QSTR)
#define FLASH_SMEM ((SH_V + 2*FK*QSTR) * 2)

__global__ void __launch_bounds__(256, 2)
flash_attn(const __half* __restrict__ Qg, const __half* __restrict__ Kg,
           const __half* __restrict__ Vg, __half* __restrict__ Og, float scale2)
{
    extern __shared__ __half smh[];
    unsigned uS = (unsigned)__cvta_generic_to_shared(smh);

    int tid = threadIdx.x;
    int warp = tid >> 5, lane = tid & 31;
    int g = lane >> 2, tg = lane & 3;
    int wm = warp * 16;

    int z  = blockIdx.y;
    int bb = z / NH, hh = z % NH;
    long tok0 = (long)bb * S_LEN + blockIdx.x * 128;
    const __half* Qb = Qg + tok0 * HIDV + hh * HD;
    const __half* Kb = Kg + (long)bb * S_LEN * HIDV + hh * HD;
    const __half* Vb = Vg + (long)bb * S_LEN * HIDV + hh * HD;

    #pragma unroll
    for (int i = 0; i < 8; i++) {
        int s = tid + i * 256;
        int row = s >> 4, ch = s & 15;
        CP_ASYNC16(uS + (SH_Q + row * QSTR + ch * 8) * 2,
                   Qb + (long)row * HIDV + ch * 8);
    }
    CP_COMMIT();

    auto issueKV = [&](int st, int kt) {
        #pragma unroll
        for (int i = 0; i < 4; i++) {
            int s = tid + i * 256;
            int row = s >> 4, ch = s & 15;
            long goff = (long)(kt * FK + row) * HIDV + ch * 8;
            CP_ASYNC16(uS + (SH_K + st * FK * QSTR + row * QSTR + ch * 8) * 2, Kb + goff);
            CP_ASYNC16(uS + (SH_V + st * FK * QSTR + row * QSTR + ch * 8) * 2, Vb + goff);
        }
        CP_COMMIT();
    };
    issueKV(0, 0);

    float m0 = -1e30f, m1 = -1e30f, l0 = 0.f, l1 = 0.f;
    float o[16][4];
    #pragma unroll
    for (int j = 0; j < 16; j++)
        #pragma unroll
        for (int r = 0; r < 4; r++) o[j][r] = 0.f;

    int aRow = lane & 15;
    int aK   = (lane >> 4) * 8;
    int bRow = (lane & 7) + ((lane >> 4) & 1) * 8;
    int bK   = ((lane >> 3) & 1) * 8;
    int vK   = (lane & 7) + ((lane >> 3) & 1) * 8;
    int vN   = ((lane >> 4) & 1) * 8;

    for (int kt = 0; kt < S_LEN / FK; kt++) {
        CP_WAIT(0);
        __syncthreads();
        if (kt + 1 < S_LEN / FK) issueKV((kt + 1) & 1, kt + 1);

        int kOff = SH_K + (kt & 1) * FK * QSTR;
        int vOff = SH_V + (kt & 1) * FK * QSTR;

        float s_acc[8][4];
        #pragma unroll
        for (int j = 0; j < 8; j++)
            #pragma unroll
            for (int r = 0; r < 4; r++) s_acc[j][r] = 0.f;

        #pragma unroll
        for (int ks = 0; ks < 8; ks++) {
            int kb = ks * 16;
            unsigned a[4];
            LDSM_X4(a[0], a[1], a[2], a[3],
                uS + (SH_Q + (wm + aRow) * QSTR + kb + aK) * 2);
            #pragma unroll
            for (int jg = 0; jg < 4; jg++) {
                unsigned p0[2], p1[2];
                LDSM_X4(p0[0], p0[1], p1[0], p1[1],
                    uS + (kOff + (jg*16 + bRow) * QSTR + kb + bK) * 2);
                MMA_F16(s_acc[2*jg],   a, p0);
                MMA_F16(s_acc[2*jg+1], a, p1);
            }
        }

        #pragma unroll
        for (int j = 0; j < 8; j++)
            #pragma unroll
            for (int r = 0; r < 4; r++) s_acc[j][r] *= scale2;

        float mx0 = -1e30f, mx1 = -1e30f;
        #pragma unroll
        for (int j = 0; j < 8; j++) {
            mx0 = fmaxf(mx0, fmaxf(s_acc[j][0], s_acc[j][1]));
            mx1 = fmaxf(mx1, fmaxf(s_acc[j][2], s_acc[j][3]));
        }
        mx0 = fmaxf(mx0, __shfl_xor_sync(0xffffffffu, mx0, 1));
        mx0 = fmaxf(mx0, __shfl_xor_sync(0xffffffffu, mx0, 2));
        mx1 = fmaxf(mx1, __shfl_xor_sync(0xffffffffu, mx1, 1));
        mx1 = fmaxf(mx1, __shfl_xor_sync(0xffffffffu, mx1, 2));

        float mn0 = fmaxf(m0, mx0), mn1 = fmaxf(m1, mx1);
        float al0 = exp2f(m0 - mn0), al1 = exp2f(m1 - mn1);
        float sum0 = 0.f, sum1 = 0.f;
        #pragma unroll
        for (int j = 0; j < 8; j++) {
            __half2 e0 = h2exp2(__floats2half2_rn(s_acc[j][0] - mn0, s_acc[j][1] - mn0));
            __half2 e1 = h2exp2(__floats2half2_rn(s_acc[j][2] - mn1, s_acc[j][3] - mn1));
            float2 f0 = __half22float2(e0);
            float2 f1 = __half22float2(e1);
            sum0 += f0.x + f0.y;
            sum1 += f1.x + f1.y;
            s_acc[j][0] = __uint_as_float(*(uint32_t*)&e0);
            s_acc[j][1] = __uint_as_float(*(uint32_t*)&e1);
        }
        sum0 += __shfl_xor_sync(0xffffffffu, sum0, 1);
        sum0 += __shfl_xor_sync(0xffffffffu, sum0, 2);
        sum1 += __shfl_xor_sync(0xffffffffu, sum1, 1);
        sum1 += __shfl_xor_sync(0xffffffffu, sum1, 2);
        l0 = l0 * al0 + sum0;
        l1 = l1 * al1 + sum1;
        m0 = mn0; m1 = mn1;
        #pragma unroll
        for (int j = 0; j < 16; j++) {
            o[j][0] *= al0; o[j][1] *= al0;
            o[j][2] *= al1; o[j][3] *= al1;
        }

        #pragma unroll
        for (int ks = 0; ks < 4; ks++) {
            unsigned a[4];
            a[0] = __float_as_uint(s_acc[2*ks][0]);
            a[1] = __float_as_uint(s_acc[2*ks][1]);
            a[2] = __float_as_uint(s_acc[2*ks+1][0]);
            a[3] = __float_as_uint(s_acc[2*ks+1][1]);
            int kb = ks * 16;
            #pragma unroll
            for (int ng = 0; ng < 8; ng++) {
                unsigned p0[2], p1[2];
                LDSM_X4_T(p0[0], p0[1], p1[0], p1[1],
                    uS + (vOff + (kb + vK) * QSTR + ng*16 + vN) * 2);
                MMA_F16(o[2*ng],   a, p0);
                MMA_F16(o[2*ng+1], a, p1);
            }
        }
    }

    float inv0 = 1.0f / l0, inv1 = 1.0f / l1;
    __half* Ob = Og + tok0 * HIDV + hh * HD;
    #pragma unroll
    for (int j = 0; j < 16; j++) {
        int col = j * 8 + tg * 2;
        *(__half2*)&Ob[(long)(wm + g) * HIDV + col] =
            __floats2half2_rn(o[j][0] * inv0, o[j][1] * inv0);
        *(__half2*)&Ob[(long)(wm + 8 + g) * HIDV + col] =
            __floats2half2_rn(o[j][2] * inv1, o[j][3] * inv1);
    }
}

// ---------------------------------------------------------------------------
extern "C" void kernel_launch(void* const* d_in, const int* in_sizes, int n_in,
                              void* d_out, int out_size)
{
    const float* hid  = (const float*)d_in[0];
    const float* Wdkv = (const float*)d_in[1];
    const float* bdkv = (const float*)d_in[2];
    const float* Wuk  = (const float*)d_in[3];
    const float* buk  = (const float*)d_in[4];
    const float* Wuv  = (const float*)d_in[5];
    const float* buv  = (const float*)d_in[6];
    const float* Wkr  = (const float*)d_in[7];
    const float* bkr  = (const float*)d_in[8];
    const float* Wdq  = (const float*)d_in[9];
    const float* bdq  = (const float*)d_in[10];
    const float* Wuq  = (const float*)d_in[11];
    const float* buq  = (const float*)d_in[12];
    // d_in[13..14] = W_QR — dead (q_r unused in reference)
    const float* Wo   = (const float*)d_in[15];
    const float* bo   = (const float*)d_in[16];

    float* out  = (float*)d_out;
    float* c_kv = out  + (long)NTOK * HIDV;
    float* kr   = c_kv + (long)NTOK * KVC;

    __half *h16, *ckv16, *cq16, *k16, *v16, *q16, *a16, *w16;
    float  *wkrT;
    cudaGetSymbolAddress((void**)&h16,   g_h16);
    cudaGetSymbolAddress((void**)&ckv16, g_ckv16);
    cudaGetSymbolAddress((void**)&cq16,  g_cq16);
    cudaGetSymbolAddress((void**)&k16,   g_k16);
    cudaGetSymbolAddress((void**)&v16,   g_v16);
    cudaGetSymbolAddress((void**)&q16,   g_q16);
    cudaGetSymbolAddress((void**)&a16,   g_a16);
    cudaGetSymbolAddress((void**)&w16,   g_w16);
    cudaGetSymbolAddress((void**)&wkrT,  g_wkrT);

    const float scale2 = 0.08838834764831845f * 1.4426950408889634f;

    static int attr_set = 0;
    static cudaStream_t s1;
    static cudaEvent_t evFork, evL2, evJoin;
    if (!attr_set) {
        cudaFuncSetAttribute(gemm_h,
            cudaFuncAttributeMaxDynamicSharedMemorySize, GEMM_SMEM);
        cudaFuncSetAttribute(flash_attn,
            cudaFuncAttributeMaxDynamicSharedMemorySize, FLASH_SMEM);
        cudaStreamCreateWithFlags(&s1, cudaStreamNonBlocking);
        cudaEventCreateWithFlags(&evFork, cudaEventDisableTiming);
        cudaEventCreateWithFlags(&evL2,   cudaEventDisableTiming);
        cudaEventCreateWithFlags(&evJoin, cudaEventDisableTiming);
        attr_set = 1;
    }

    // ---- fork side stream for input-only work (wkr_t) ----
    cudaEventRecord(evFork, 0);
    cudaStreamWaitEvent(s1, evFork, 0);
    wkr_t<<<(HD*RR + 255) / 256, 256, 0, s1>>>(Wkr, wkrT);

    // main stream: conversions
    {
        C7 j;
        const float* srcs[7] = { hid, Wdkv, Wuk, Wuv, Wdq, Wuq, Wo };
        __half* dsts[7] = { h16, w16 + OFF_DKV, w16 + OFF_UK, w16 + OFF_UV,
                            w16 + OFF_DQ, w16 + OFF_UQ, w16 + OFF_O };
        int sizes[7] = { NTOK*HIDV, KVC*HIDV, HIDV*KVC, HIDV*KVC,
                         QCV*HIDV, HIDV*QCV, HIDV*HIDV };
        int cum = 0;
        for (int k = 0; k < 7; k++) {
            j.s[k] = (const float4*)srcs[k];
            j.d[k] = (__half2*)dsts[k];
            j.cum[k] = cum;
            cum += sizes[k] / 4;
        }
        j.cum[7] = cum;
        cvt_multi<<<(cum + 255) / 256, 256>>>(j);
    }

    // L1: c_kv + c_q, K=2048
    {
        Job ja = { h16, w16 + OFF_DKV, bdkv, c_kv,   ckv16, HIDV, HIDV, HIDV, KVC };
        Job jb = { h16, w16 + OFF_DQ,  bdq,  nullptr, cq16, HIDV, HIDV, HIDV, QCV };
        gemm_h<<<dim3(16, NTOK/BM), 256, GEMM_SMEM>>>(ja, jb, jb, 4, 16);
    }

    // L2: k + v (K=512) + q (K=1536)
    {
        Job ja = { ckv16, w16 + OFF_UK, buk, nullptr, k16, KVC, KVC, KVC, HIDV };
        Job jb = { ckv16, w16 + OFF_UV, buv, nullptr, v16, KVC, KVC, KVC, HIDV };
        Job jc = { cq16,  w16 + OFF_UQ, buq, nullptr, q16, QCV, QCV, QCV, HIDV };
        gemm_h<<<dim3(48, NTOK/BM), 256, GEMM_SMEM>>>(ja, jb, jc, 16, 32);
    }

    // fork: kr_rope (needs k16 from L2 + wkrT already on s1) runs
    // concurrently with flash_attn on the main stream
    cudaEventRecord(evL2, 0);
    cudaStreamWaitEvent(s1, evL2, 0);
    kr_rope2<<<NTOK * NH / KR_G, 128, 0, s1>>>(k16, wkrT, bkr, kr);

    // flash attention on main stream
    flash_attn<<<dim3(S_LEN/128, BATCH*NH), 256, FLASH_SMEM>>>(
        q16, k16, v16, a16, scale2);

    // join side stream before final GEMM (graph fork must rejoin)
    cudaEventRecord(evJoin, s1);
    cudaStreamWaitEvent(0, evJoin, 0);

    // L4: output = attn @ W_O^T + b
    {
        Job ja = { a16, w16 + OFF_O, bo, out, nullptr, HIDV, HIDV, HIDV, HIDV };
        gemm_h<<<dim3(16, NTOK/BM), 256, GEMM_SMEM>>>(ja, ja, ja, 16, 16);
    }
}